// round 1
// baseline (speedup 1.0000x reference)
#include <cuda_runtime.h>

// YOLO loss reduction on B200 (sm_100a).
// loss = sum over cells of:
//   mask(gt[...,4]==1) ? 5*sum((pre[...,0:4]-gt[...,0:4])^2) + 10*(pre4-gt4)^2
//                      : 0.5*(pre4-gt4)^2
//
// Only channels 0..4 of 30 are needed -> request only those bytes (min DRAM
// traffic ~308MB vs 771MB full read). Staging: linear index over "needed
// elements" (5 per cell) gives near-coalesced gathers (~10 sectors per warp
// LDG instead of 32). SMEM stride-5 reads are bank-conflict-free (gcd(5,32)=1).
//
// Deterministic reduction: per-block double partials into a __device__ array
// (no device allocs, no atomics on the output), then a single-block fold.

#define TPB 256
#define CELLS_PER_TILE 256          // == TPB, one cell per thread per tile
#define MAX_BLOCKS 4096

__device__ double g_partials[MAX_BLOCKS];

__global__ __launch_bounds__(TPB)
void yolo_loss_partial(const float* __restrict__ pre,
                       const float* __restrict__ gt,
                       int ncells, int ntiles) {
    __shared__ float sp[CELLS_PER_TILE * 5];
    __shared__ float sg[CELLS_PER_TILE * 5];
    __shared__ double swarp[TPB / 32];

    double acc = 0.0;

    for (int tile = blockIdx.x; tile < ntiles; tile += gridDim.x) {
        const int cell0 = tile * CELLS_PER_TILE;

        // ---- stage: gather the 5 needed channels of 256 cells, both tensors
        #pragma unroll
        for (int k = 0; k < 5; ++k) {
            int i = threadIdx.x + k * TPB;          // i in [0, 1280)
            int c  = i / 5;                          // cell within tile
            int ch = i - c * 5;                      // channel 0..4
            int g  = cell0 + c;                      // global cell
            float vp = 0.0f, vg = 0.0f;
            if (g < ncells) {
                size_t off = (size_t)g * 30 + (size_t)ch;
                vp = __ldg(pre + off);
                vg = __ldg(gt  + off);
            }
            sp[i] = vp;
            sg[i] = vg;
        }
        __syncthreads();

        // ---- compute: one cell per thread, stride-5 smem reads (conflict-free)
        {
            const int li = threadIdx.x;
            const int b  = li * 5;
            float p0 = sp[b+0], p1 = sp[b+1], p2 = sp[b+2], p3 = sp[b+3], p4 = sp[b+4];
            float q0 = sg[b+0], q1 = sg[b+1], q2 = sg[b+2], q3 = sg[b+3], q4 = sg[b+4];

            float d0 = p0 - q0, d1 = p1 - q1, d2 = p2 - q2, d3 = p3 - q3;
            float coord = fmaf(d0, d0, fmaf(d1, d1, fmaf(d2, d2, d3 * d3)));
            float dc = p4 - q4;
            float conf = dc * dc;

            float cell_loss = (q4 == 1.0f) ? fmaf(5.0f, coord, 10.0f * conf)
                                           : 0.5f * conf;
            if (cell0 + li < ncells) acc += (double)cell_loss;
        }
        __syncthreads();
    }

    // ---- block reduction (double), write one partial per block
    const unsigned full = 0xffffffffu;
    #pragma unroll
    for (int s = 16; s > 0; s >>= 1) acc += __shfl_down_sync(full, acc, s);
    if ((threadIdx.x & 31) == 0) swarp[threadIdx.x >> 5] = acc;
    __syncthreads();
    if (threadIdx.x < 32) {
        double v = (threadIdx.x < (TPB / 32)) ? swarp[threadIdx.x] : 0.0;
        #pragma unroll
        for (int s = 16; s > 0; s >>= 1) v += __shfl_down_sync(full, v, s);
        if (threadIdx.x == 0) g_partials[blockIdx.x] = v;
    }
}

__global__ __launch_bounds__(256)
void yolo_loss_final(float* __restrict__ out, int nblocks) {
    __shared__ double swarp[8];
    double acc = 0.0;
    for (int i = threadIdx.x; i < nblocks; i += 256) acc += g_partials[i];

    const unsigned full = 0xffffffffu;
    #pragma unroll
    for (int s = 16; s > 0; s >>= 1) acc += __shfl_down_sync(full, acc, s);
    if ((threadIdx.x & 31) == 0) swarp[threadIdx.x >> 5] = acc;
    __syncthreads();
    if (threadIdx.x < 32) {
        double v = (threadIdx.x < 8) ? swarp[threadIdx.x] : 0.0;
        #pragma unroll
        for (int s = 16; s > 0; s >>= 1) v += __shfl_down_sync(full, v, s);
        if (threadIdx.x == 0) out[0] = (float)v;
    }
}

extern "C" void kernel_launch(void* const* d_in, const int* in_sizes, int n_in,
                              void* d_out, int out_size) {
    const float* pre = (const float*)d_in[0];          // label_pre
    const float* gt  = (const float*)d_in[1];          // label_ground_truth
    float* out = (float*)d_out;

    const int nelem  = in_sizes[0];                    // B*S*S*C
    const int ncells = nelem / 30;                     // B*S*S
    const int ntiles = (ncells + CELLS_PER_TILE - 1) / CELLS_PER_TILE;

    int nblocks = ntiles < MAX_BLOCKS ? ntiles : MAX_BLOCKS;
    if (nblocks > 2048) nblocks = 2048;                // ~6 tiles/block, 2 waves

    yolo_loss_partial<<<nblocks, TPB>>>(pre, gt, ncells, ntiles);
    yolo_loss_final<<<1, 256>>>(out, nblocks);
}